// round 14
// baseline (speedup 1.0000x reference)
#include <cuda_runtime.h>
#include <math.h>

#define RR 273
#define CC 256
#define KK 219
#define KKP 224          // padded sel stride
#define RRP 288          // padded newid stride
#define NT1 256          // K1 threads
#define NW1 8            // K1 warps
#define HB 280
#define FULLM 0xFFFFFFFFu
#define GMAX 1024
#define EMAX (GMAX * 273 * 32)

__device__ unsigned int   g_packed[EMAX];       // packed local ids (src<<16|dst)
__device__ float          g_h[GMAX * RR];       // gcn linear output
__device__ unsigned short g_sel[GMAX * KKP];    // rank -> node id
__device__ short          g_newid[GMAX * RRP];  // node -> new id (-1 dropped)

__device__ __forceinline__ unsigned int ord_f32(float f) {
    unsigned int u = __float_as_uint(f);
    return (u & 0x80000000u) ? ~u : (u | 0x80000000u);
}

// ===== K0: h = x . W, Eigen NEON gemv arithmetic, one thread per row =====
__global__ __launch_bounds__(256)
void k0_linear(const float* __restrict__ x, const float* __restrict__ Wp,
               long long Nrows)
{
    __shared__ float wsh[CC];
    if (threadIdx.x < CC) wsh[threadIdx.x] = Wp[threadIdx.x];
    __syncthreads();
    long long row = (long long)blockIdx.x * 256 + threadIdx.x;
    if (row >= Nrows) return;
    const float4* w4 = (const float4*)wsh;
    const float4* xr = (const float4*)(x + row * CC);
    float a0 = 0.f, a1 = 0.f, a2 = 0.f, a3 = 0.f;
    #pragma unroll 4
    for (int i = 0; i < 64; i++) {
        float4 v = xr[i];
        float4 w = w4[i];
        a0 = fmaf(v.x, w.x, a0);
        a1 = fmaf(v.y, w.y, a1);
        a2 = fmaf(v.z, w.z, a2);
        a3 = fmaf(v.w, w.w, a3);
    }
    g_h[row] = __fadd_rn(__fadd_rn(a0, a2), __fadd_rn(a1, a3));
}

// ===== K1: per-graph scoring + top-K selection =====
__global__ __launch_bounds__(NT1, 3)
void k1_score(const void* __restrict__ edge_index,
              const float* __restrict__ bp,
              float* __restrict__ out,
              long long E, int epg, size_t off_score)
{
    extern __shared__ char smem[];
    float* h_s   = (float*)smem;                        // 288
    float* dis_s = h_s + RRP;                           // 288
    float* sc_s  = dis_s + RRP;                         // 288
    int* indeg_s = (int*)(sc_s + RRP);                  // 288
    int* start_s = indeg_s + RRP;                       // 288
    int* flag_s  = start_s + RRP;                       // 8
    unsigned short* hist = (unsigned short*)(flag_s + 8);     // NW1*HB u16
    unsigned int* ed = (unsigned int*)(((size_t)(hist + NW1 * HB) + 7) & ~(size_t)7); // epg
    char* ub = (char*)(ed + epg);
    unsigned short* ssrc = (unsigned short*)ub;               // epg u16 (alive thru score)
    unsigned long long* keys = (unsigned long long*)ub;       // 288 u64 (after)

    const int tid  = threadIdx.x;
    const int lane = tid & 31;
    const int warp = tid >> 5;
    const int g    = blockIdx.x;
    const long long gbase = (long long)g * RR;

    // init + self-probe dtype
    for (int i = tid; i < NW1 * HB; i += NT1) hist[i] = 0;
    if (tid == 0) {
        const int* p32 = (const int*)edge_index;
        int all_zero = 1;
        #pragma unroll
        for (int i = 1; i < 32; i += 2)
            if (p32[i] != 0) { all_zero = 0; break; }
        *flag_s = all_zero;
    }
    // load h
    for (int v = tid; v < RR; v += NT1) h_s[v] = g_h[gbase + v];
    __syncthreads();
    const int is64 = *flag_s;

    // edge load -> pack to smem + gmem scratch
    {
        const long long ebase = (long long)g * epg;
        if (is64) {
            const long long* p = (const long long*)edge_index;
            for (int e = tid; e < epg; e += NT1) {
                int ls = (int)(p[ebase + e] - gbase);
                int ld = (int)(p[ebase + E + e] - gbase);
                unsigned pk = ((unsigned)ls << 16) | (unsigned)ld;
                ed[e] = pk;
                g_packed[ebase + e] = pk;
            }
        } else {
            const int* p = (const int*)edge_index;
            for (int e = tid; e < epg; e += NT1) {
                int ls = (int)(p[ebase + e] - gbase);
                int ld = (int)(p[ebase + E + e] - gbase);
                unsigned pk = ((unsigned)ls << 16) | (unsigned)ld;
                ed[e] = pk;
                g_packed[ebase + e] = pk;
            }
        }
    }
    __syncthreads();

    // stable counting sort by dst
    const int per = (((epg + NW1 - 1) / NW1) + 31) & ~31;
    const int cbeg = warp * per;
    const int cend = min(epg, cbeg + per);

    for (int base = cbeg; base < cend; base += 32) {
        int e = base + lane;
        bool act = e < cend;
        unsigned v = act ? ed[e] : 0u;
        int dst = act ? (int)(v & 0xFFFFu) : (512 + lane);
        unsigned m = __match_any_sync(FULLM, dst);
        int leader = __ffs(m) - 1;
        if (act && lane == leader)
            hist[warp * HB + dst] = (unsigned short)(hist[warp * HB + dst] + __popc(m));
        __syncwarp();
    }
    __syncthreads();

    for (int v = tid; v < RR; v += NT1) {
        int s = 0;
        #pragma unroll
        for (int w2 = 0; w2 < NW1; w2++) s += hist[w2 * HB + v];
        indeg_s[v] = s;
        dis_s[v] = __fdiv_rn(1.0f, __fsqrt_rn((float)(s + 1)));
    }
    __syncthreads();

    if (warp == 0) {
        int lo = lane * 9;
        int acc = 0;
        #pragma unroll
        for (int i = 0; i < 9; i++) { int v = lo + i; if (v < RR) acc += indeg_s[v]; }
        int ex = acc;
        #pragma unroll
        for (int o = 1; o < 32; o <<= 1) {
            int t = __shfl_up_sync(FULLM, ex, o);
            if (lane >= o) ex += t;
        }
        ex -= acc;
        int run = ex;
        #pragma unroll
        for (int i = 0; i < 9; i++) {
            int v = lo + i;
            if (v < RR) { start_s[v] = run; run += indeg_s[v]; }
        }
    }
    __syncthreads();

    for (int v = tid; v < RR; v += NT1) {
        int s = start_s[v];
        #pragma unroll
        for (int w2 = 0; w2 < NW1; w2++) {
            int t = hist[w2 * HB + v];
            hist[w2 * HB + v] = (unsigned short)s;
            s += t;
        }
    }
    __syncthreads();

    for (int base = cbeg; base < cend; base += 32) {
        int e = base + lane;
        bool act = e < cend;
        unsigned v = act ? ed[e] : 0u;
        int dst = act ? (int)(v & 0xFFFFu) : (512 + lane);
        unsigned m = __match_any_sync(FULLM, dst);
        int rank = __popc(m & ((1u << lane) - 1u));
        int pos = 0;
        if (act) pos = (int)hist[warp * HB + dst] + rank;
        __syncwarp();
        if (act) ssrc[pos] = (unsigned short)(v >> 16);
        int leader = __ffs(m) - 1;
        if (act && lane == leader)
            hist[warp * HB + dst] = (unsigned short)(hist[warp * HB + dst] + __popc(m));
        __syncwarp();
    }
    __syncthreads();

    // score: strictly sequential in reference scatter order (2 nodes/thread)
    const float bval = bp[0];
    for (int v = tid; v < RR; v += NT1) {
        float dv = dis_s[v];
        float acc = 0.f;
        int st = start_s[v], n = indeg_s[v];
        for (int i = 0; i < n; i++) {
            int src = ssrc[st + i];
            float c = __fmul_rn(__fmul_rn(dis_s[src], dv), h_s[src]);
            acc = __fadd_rn(acc, c);
        }
        float selfc = __fmul_rn(__fmul_rn(dv, dv), h_s[v]);
        acc = __fadd_rn(acc, selfc);
        float sc = __fadd_rn(acc, bval);
        sc_s[v] = sc;
        out[off_score + (size_t)gbase + v] = sc;
    }
    __syncthreads();   // ssrc dead

    // rank keys (unique)
    for (int v = tid; v < RR; v += NT1)
        keys[v] = ((unsigned long long)ord_f32(sc_s[v]) << 32)
                  | (unsigned long long)(0x1FFu - (unsigned)v);
    __syncthreads();

    // rank-based top-K selection
    for (int v = tid; v < RR; v += NT1) {
        unsigned long long mk = keys[v];
        int rank = 0;
        #pragma unroll 3
        for (int u = 0; u < RR; u++)
            rank += (keys[u] > mk) ? 1 : 0;
        short nid = (rank < KK) ? (short)rank : (short)-1;
        g_newid[g * RRP + v] = nid;
        if (rank < KK) g_sel[g * KKP + rank] = (unsigned short)v;
    }
}

// ===== K2: gather x_new / perm / batch (one warp per output row) =====
__global__ __launch_bounds__(256)
void k2_gather(const float* __restrict__ x,
               float* __restrict__ out,
               size_t off_batch, size_t off_perm, size_t off_score,
               int total_rows)
{
    const int lane = threadIdx.x & 31;
    const int wid  = blockIdx.x * 8 + (threadIdx.x >> 5);
    if (wid >= total_rows) return;
    const int g = wid / KK;
    const int k = wid - g * KK;
    const int v = g_sel[g * KKP + k];
    const long long gbase = (long long)g * RR;
    float sc = out[off_score + (size_t)gbase + v];
    float t = tanhf(sc);
    const float4* srcp = (const float4*)(x + ((size_t)(gbase + v)) * CC);
    float4* dstp = (float4*)(out + (size_t)wid * CC);
    float4 a0 = srcp[lane];
    float4 a1 = srcp[lane + 32];
    a0.x *= t; a0.y *= t; a0.z *= t; a0.w *= t;
    a1.x *= t; a1.y *= t; a1.z *= t; a1.w *= t;
    dstp[lane] = a0;
    dstp[lane + 32] = a1;
    if (lane == 0) {
        out[off_perm  + wid] = (float)(gbase + v);
        out[off_batch + wid] = (float)g;
    }
}

// ===== K3: edge remap + keep (one block per graph) =====
__global__ __launch_bounds__(256)
void k3_remap(float* __restrict__ out,
              long long E, int epg, size_t off_ei, size_t off_keep)
{
    __shared__ short nid[RRP];
    const int tid = threadIdx.x;
    const int g = blockIdx.x;
    for (int v = tid; v < RR; v += 256) nid[v] = g_newid[g * RRP + v];
    __syncthreads();
    const size_t ebase = (size_t)g * epg;
    const int gk = g * KK;
    for (int e = tid; e < epg; e += 256) {
        unsigned v = g_packed[ebase + e];
        int ns = nid[v >> 16];
        int nd = nid[v & 0xFFFFu];
        size_t ge = ebase + e;
        bool kp = (ns >= 0) & (nd >= 0);
        out[off_ei + ge]             = kp ? (float)(gk + ns) : -1.0f;
        out[off_ei + (size_t)E + ge] = kp ? (float)(gk + nd) : -1.0f;
        out[off_keep + ge]           = kp ? 1.0f : 0.0f;
    }
}

extern "C" void kernel_launch(void* const* d_in, const int* in_sizes, int n_in,
                              void* d_out, int out_size)
{
    const float* x  = (const float*)d_in[0];
    const void*  ei = d_in[1];
    const float* W  = (const float*)d_in[3];
    const float* b  = (const float*)d_in[4];

    long long N = (long long)in_sizes[0] / CC;
    long long E = (long long)in_sizes[1] / 2;
    int G   = (int)(N / RR);
    int epg = (int)(E / G);

    float* out = (float*)d_out;
    size_t GK        = (size_t)G * KK;
    size_t off_ei    = GK * CC;
    size_t off_keep  = off_ei + 2 * (size_t)E;
    size_t off_batch = off_keep + (size_t)E;
    size_t off_perm  = off_batch + GK;
    size_t off_score = off_perm + GK;

    // K1 dynamic smem
    size_t fixed = 5 * RRP * 4 + 8 * 4 + (size_t)NW1 * HB * 2 + 8;
    size_t edB   = (size_t)epg * 4;
    size_t keysB = (size_t)RRP * 8;
    size_t uB    = ((size_t)epg * 2 > keysB) ? (size_t)epg * 2 : keysB;
    size_t smem1 = fixed + edB + uB + 64;

    static int attr_set = 0;
    if (!attr_set) {
        cudaFuncSetAttribute(k1_score,
                             cudaFuncAttributeMaxDynamicSharedMemorySize,
                             (int)smem1);
        attr_set = 1;
    }

    int gridK0 = (int)((N + 255) / 256);
    int totalRows = (int)GK;
    int gridK2 = (totalRows + 7) / 8;

    k0_linear<<<gridK0, 256>>>(x, W, N);
    k1_score<<<G, NT1, smem1>>>(ei, b, out, E, epg, off_score);
    k2_gather<<<gridK2, 256>>>(x, out, off_batch, off_perm, off_score, totalRows);
    k3_remap<<<G, 256>>>(out, E, epg, off_ei, off_keep);
}

// round 15
// speedup vs baseline: 1.0384x; 1.0384x over previous
#include <cuda_runtime.h>
#include <math.h>

#define RR 273
#define CC 256
#define KK 219
#define KKP 224
#define RRP 288
#define NT1 256
#define NW1 8
#define HB 280
#define FULLM 0xFFFFFFFFu
#define GMAX 1024
#define EMAX (GMAX * 273 * 32)

__device__ unsigned int   g_packed[EMAX];        // packed local ids (src<<16|dst)
__device__ unsigned short g_ssrc[EMAX];          // dst-sorted src lists
__device__ float          g_h[GMAX * RR];
__device__ unsigned short g_indeg[GMAX * RRP];
__device__ unsigned short g_start[GMAX * RRP];
__device__ unsigned short g_sel[GMAX * KKP];
__device__ short          g_newid[GMAX * RRP];

__device__ __forceinline__ unsigned int ord_f32(float f) {
    unsigned int u = __float_as_uint(f);
    return (u & 0x80000000u) ? ~u : (u | 0x80000000u);
}

// ===== K0: h = x . W (Eigen NEON gemv arithmetic), one thread per row =====
__global__ __launch_bounds__(256)
void k0_linear(const float* __restrict__ x, const float* __restrict__ Wp,
               long long Nrows)
{
    __shared__ float wsh[CC];
    if (threadIdx.x < CC) wsh[threadIdx.x] = Wp[threadIdx.x];
    __syncthreads();
    long long row = (long long)blockIdx.x * 256 + threadIdx.x;
    if (row >= Nrows) return;
    const float4* w4 = (const float4*)wsh;
    const float4* xr = (const float4*)(x + row * CC);
    float a0 = 0.f, a1 = 0.f, a2 = 0.f, a3 = 0.f;
    #pragma unroll 4
    for (int i = 0; i < 64; i++) {
        float4 v = xr[i];
        float4 w = w4[i];
        a0 = fmaf(v.x, w.x, a0);
        a1 = fmaf(v.y, w.y, a1);
        a2 = fmaf(v.z, w.z, a2);
        a3 = fmaf(v.w, w.w, a3);
    }
    g_h[row] = __fadd_rn(__fadd_rn(a0, a2), __fadd_rn(a1, a3));
}

// ===== K1a: edge pack + stable counting sort by dst (no h needed) =====
__global__ __launch_bounds__(NT1, 3)
void k1a_sort(const void* __restrict__ edge_index, long long E, int epg)
{
    extern __shared__ char smem[];
    int* indeg_s = (int*)smem;                           // RRP
    int* start_s = indeg_s + RRP;                        // RRP
    int* flag_s  = start_s + RRP;                        // 8
    unsigned short* hist = (unsigned short*)(flag_s + 8);      // NW1*HB
    unsigned int* ed = (unsigned int*)(((size_t)(hist + NW1 * HB) + 7) & ~(size_t)7);
    unsigned short* ssrc = (unsigned short*)(ed + epg);

    const int tid  = threadIdx.x;
    const int lane = tid & 31;
    const int warp = tid >> 5;
    const int g    = blockIdx.x;
    const long long gbase = (long long)g * RR;
    const long long ebase = (long long)g * epg;

    for (int i = tid; i < NW1 * HB; i += NT1) hist[i] = 0;
    if (tid == 0) {
        const int* p32 = (const int*)edge_index;
        int all_zero = 1;
        #pragma unroll
        for (int i = 1; i < 32; i += 2)
            if (p32[i] != 0) { all_zero = 0; break; }
        *flag_s = all_zero;
    }
    __syncthreads();
    const int is64 = *flag_s;

    if (is64) {
        const long long* p = (const long long*)edge_index;
        for (int e = tid; e < epg; e += NT1) {
            int ls = (int)(p[ebase + e] - gbase);
            int ld = (int)(p[ebase + E + e] - gbase);
            unsigned pk = ((unsigned)ls << 16) | (unsigned)ld;
            ed[e] = pk;
            g_packed[ebase + e] = pk;
        }
    } else {
        const int* p = (const int*)edge_index;
        for (int e = tid; e < epg; e += NT1) {
            int ls = (int)(p[ebase + e] - gbase);
            int ld = (int)(p[ebase + E + e] - gbase);
            unsigned pk = ((unsigned)ls << 16) | (unsigned)ld;
            ed[e] = pk;
            g_packed[ebase + e] = pk;
        }
    }
    __syncthreads();

    const int per = (((epg + NW1 - 1) / NW1) + 31) & ~31;
    const int cbeg = warp * per;
    const int cend = min(epg, cbeg + per);

    // pass 1: per-warp-chunk histograms (deterministic)
    for (int base = cbeg; base < cend; base += 32) {
        int e = base + lane;
        bool act = e < cend;
        unsigned v = act ? ed[e] : 0u;
        int dst = act ? (int)(v & 0xFFFFu) : (512 + lane);
        unsigned m = __match_any_sync(FULLM, dst);
        int leader = __ffs(m) - 1;
        if (act && lane == leader)
            hist[warp * HB + dst] = (unsigned short)(hist[warp * HB + dst] + __popc(m));
        __syncwarp();
    }
    __syncthreads();

    for (int v = tid; v < RR; v += NT1) {
        int s = 0;
        #pragma unroll
        for (int w2 = 0; w2 < NW1; w2++) s += hist[w2 * HB + v];
        indeg_s[v] = s;
    }
    __syncthreads();

    if (warp == 0) {
        int lo = lane * 9;
        int acc = 0;
        #pragma unroll
        for (int i = 0; i < 9; i++) { int v = lo + i; if (v < RR) acc += indeg_s[v]; }
        int ex = acc;
        #pragma unroll
        for (int o = 1; o < 32; o <<= 1) {
            int t = __shfl_up_sync(FULLM, ex, o);
            if (lane >= o) ex += t;
        }
        ex -= acc;
        int run = ex;
        #pragma unroll
        for (int i = 0; i < 9; i++) {
            int v = lo + i;
            if (v < RR) { start_s[v] = run; run += indeg_s[v]; }
        }
    }
    __syncthreads();

    for (int v = tid; v < RR; v += NT1) {
        int s = start_s[v];
        #pragma unroll
        for (int w2 = 0; w2 < NW1; w2++) {
            int t = hist[w2 * HB + v];
            hist[w2 * HB + v] = (unsigned short)s;
            s += t;
        }
    }
    __syncthreads();

    // pass 2: stable placement
    for (int base = cbeg; base < cend; base += 32) {
        int e = base + lane;
        bool act = e < cend;
        unsigned v = act ? ed[e] : 0u;
        int dst = act ? (int)(v & 0xFFFFu) : (512 + lane);
        unsigned m = __match_any_sync(FULLM, dst);
        int rank = __popc(m & ((1u << lane) - 1u));
        int pos = 0;
        if (act) pos = (int)hist[warp * HB + dst] + rank;
        __syncwarp();
        if (act) ssrc[pos] = (unsigned short)(v >> 16);
        int leader = __ffs(m) - 1;
        if (act && lane == leader)
            hist[warp * HB + dst] = (unsigned short)(hist[warp * HB + dst] + __popc(m));
        __syncwarp();
    }
    __syncthreads();

    // export sorted lists + per-node offsets (coalesced)
    for (int e = tid; e < epg; e += NT1) g_ssrc[ebase + e] = ssrc[e];
    for (int v = tid; v < RR; v += NT1) {
        g_indeg[g * RRP + v] = (unsigned short)indeg_s[v];
        g_start[g * RRP + v] = (unsigned short)start_s[v];
    }
}

// ===== K1b: score (bit-exact reference order) + rank-based top-K =====
__global__ __launch_bounds__(NT1)
void k1b_score(const float* __restrict__ bp, float* __restrict__ out,
               int epg, size_t off_score)
{
    __shared__ float h_s[RRP];
    __shared__ float dis_s[RRP];
    __shared__ float sc_s[RRP];
    __shared__ unsigned long long keys[RRP];
    __shared__ int start_sh[RRP];
    __shared__ int indeg_sh[RRP];

    const int tid = threadIdx.x;
    const int g = blockIdx.x;
    const long long gbase = (long long)g * RR;
    const long long ebase = (long long)g * epg;

    for (int v = tid; v < RR; v += NT1) {
        h_s[v] = g_h[gbase + v];
        int n = g_indeg[g * RRP + v];
        indeg_sh[v] = n;
        start_sh[v] = g_start[g * RRP + v];
        dis_s[v] = __fdiv_rn(1.0f, __fsqrt_rn((float)(n + 1)));
    }
    __syncthreads();

    const float bval = bp[0];
    for (int v = tid; v < RR; v += NT1) {
        float dv = dis_s[v];
        float acc = 0.f;
        int st = start_sh[v], n = indeg_sh[v];
        for (int i = 0; i < n; i++) {
            int src = g_ssrc[ebase + st + i];
            float c = __fmul_rn(__fmul_rn(dis_s[src], dv), h_s[src]);
            acc = __fadd_rn(acc, c);
        }
        float selfc = __fmul_rn(__fmul_rn(dv, dv), h_s[v]);
        acc = __fadd_rn(acc, selfc);
        float sc = __fadd_rn(acc, bval);
        sc_s[v] = sc;
        out[off_score + (size_t)gbase + v] = sc;
        keys[v] = ((unsigned long long)ord_f32(sc) << 32)
                  | (unsigned long long)(0x1FFu - (unsigned)v);
    }
    __syncthreads();

    for (int v = tid; v < RR; v += NT1) {
        unsigned long long mk = keys[v];
        int rank = 0;
        #pragma unroll 3
        for (int u = 0; u < RR; u++)
            rank += (keys[u] > mk) ? 1 : 0;
        short nid = (rank < KK) ? (short)rank : (short)-1;
        g_newid[g * RRP + v] = nid;
        if (rank < KK) g_sel[g * KKP + rank] = (unsigned short)v;
    }
}

// ===== K2: gather x_new / perm / batch (one warp per output row) =====
__global__ __launch_bounds__(256)
void k2_gather(const float* __restrict__ x, float* __restrict__ out,
               size_t off_batch, size_t off_perm, size_t off_score,
               int total_rows)
{
    const int lane = threadIdx.x & 31;
    const int wid  = blockIdx.x * 8 + (threadIdx.x >> 5);
    if (wid >= total_rows) return;
    const int g = wid / KK;
    const int k = wid - g * KK;
    const int v = g_sel[g * KKP + k];
    const long long gbase = (long long)g * RR;
    float sc = out[off_score + (size_t)gbase + v];
    float t = tanhf(sc);
    const float4* srcp = (const float4*)(x + ((size_t)(gbase + v)) * CC);
    float4* dstp = (float4*)(out + (size_t)wid * CC);
    float4 a0 = srcp[lane];
    float4 a1 = srcp[lane + 32];
    a0.x *= t; a0.y *= t; a0.z *= t; a0.w *= t;
    a1.x *= t; a1.y *= t; a1.z *= t; a1.w *= t;
    dstp[lane] = a0;
    dstp[lane + 32] = a1;
    if (lane == 0) {
        out[off_perm  + wid] = (float)(gbase + v);
        out[off_batch + wid] = (float)g;
    }
}

// ===== K3: edge remap + keep (one block per graph) =====
__global__ __launch_bounds__(256)
void k3_remap(float* __restrict__ out,
              long long E, int epg, size_t off_ei, size_t off_keep)
{
    __shared__ short nid[RRP];
    const int tid = threadIdx.x;
    const int g = blockIdx.x;
    for (int v = tid; v < RR; v += 256) nid[v] = g_newid[g * RRP + v];
    __syncthreads();
    const size_t ebase = (size_t)g * epg;
    const int gk = g * KK;
    for (int e = tid; e < epg; e += 256) {
        unsigned v = g_packed[ebase + e];
        int ns = nid[v >> 16];
        int nd = nid[v & 0xFFFFu];
        size_t ge = ebase + e;
        bool kp = (ns >= 0) & (nd >= 0);
        out[off_ei + ge]             = kp ? (float)(gk + ns) : -1.0f;
        out[off_ei + (size_t)E + ge] = kp ? (float)(gk + nd) : -1.0f;
        out[off_keep + ge]           = kp ? 1.0f : 0.0f;
    }
}

extern "C" void kernel_launch(void* const* d_in, const int* in_sizes, int n_in,
                              void* d_out, int out_size)
{
    const float* x  = (const float*)d_in[0];
    const void*  ei = d_in[1];
    const float* W  = (const float*)d_in[3];
    const float* b  = (const float*)d_in[4];

    long long N = (long long)in_sizes[0] / CC;
    long long E = (long long)in_sizes[1] / 2;
    int G   = (int)(N / RR);
    int epg = (int)(E / G);

    float* out = (float*)d_out;
    size_t GK        = (size_t)G * KK;
    size_t off_ei    = GK * CC;
    size_t off_keep  = off_ei + 2 * (size_t)E;
    size_t off_batch = off_keep + (size_t)E;
    size_t off_perm  = off_batch + GK;
    size_t off_score = off_perm + GK;

    // K1a dynamic smem
    size_t fixed = 2 * RRP * 4 + 8 * 4 + (size_t)NW1 * HB * 2 + 8;
    size_t smem1 = fixed + (size_t)epg * 4 + (size_t)epg * 2 + 64;

    static cudaStream_t s2 = 0;
    static cudaEvent_t evF1 = 0, evJ1 = 0, evF2 = 0, evJ2 = 0;
    static int init_done = 0;
    if (!init_done) {
        cudaFuncSetAttribute(k1a_sort,
                             cudaFuncAttributeMaxDynamicSharedMemorySize,
                             (int)smem1);
        cudaStreamCreateWithFlags(&s2, cudaStreamNonBlocking);
        cudaEventCreateWithFlags(&evF1, cudaEventDisableTiming);
        cudaEventCreateWithFlags(&evJ1, cudaEventDisableTiming);
        cudaEventCreateWithFlags(&evF2, cudaEventDisableTiming);
        cudaEventCreateWithFlags(&evJ2, cudaEventDisableTiming);
        init_done = 1;
    }

    int gridK0 = (int)((N + 255) / 256);
    int totalRows = (int)GK;
    int gridK2 = (totalRows + 7) / 8;

    // fork 1: K0 (stream 0) || K1a (s2)
    cudaEventRecord(evF1, 0);
    cudaStreamWaitEvent(s2, evF1, 0);
    k0_linear<<<gridK0, 256, 0, 0>>>(x, W, N);
    k1a_sort<<<G, NT1, smem1, s2>>>(ei, E, epg);
    cudaEventRecord(evJ1, s2);
    cudaStreamWaitEvent(0, evJ1, 0);

    // K1b (stream 0, needs h + sorted lists)
    k1b_score<<<G, NT1, 0, 0>>>(b, out, epg, off_score);

    // fork 2: K2 (stream 0) || K3 (s2)
    cudaEventRecord(evF2, 0);
    cudaStreamWaitEvent(s2, evF2, 0);
    k2_gather<<<gridK2, 256, 0, 0>>>(x, out, off_batch, off_perm, off_score, totalRows);
    k3_remap<<<G, 256, 0, s2>>>(out, E, epg, off_ei, off_keep);
    cudaEventRecord(evJ2, s2);
    cudaStreamWaitEvent(0, evJ2, 0);
}

// round 16
// speedup vs baseline: 1.0439x; 1.0053x over previous
#include <cuda_runtime.h>
#include <math.h>

#define RR 273
#define CC 256
#define KK 219
#define KKP 224
#define RRP 288
#define NT1 256
#define NW1 8
#define HB 280
#define FULLM 0xFFFFFFFFu
#define GMAX 1024
#define EMAX (GMAX * 273 * 32)

__device__ unsigned int   g_packed[EMAX];        // packed local ids (src<<16|dst)
__device__ unsigned short g_ssrc[EMAX];          // dst-sorted src lists
__device__ float          g_h[GMAX * RR];
__device__ unsigned short g_indeg[GMAX * RRP];
__device__ unsigned short g_start[GMAX * RRP];
__device__ unsigned short g_sel[GMAX * KKP];
__device__ short          g_newid[GMAX * RRP];

__device__ __forceinline__ unsigned int ord_f32(float f) {
    unsigned int u = __float_as_uint(f);
    return (u & 0x80000000u) ? ~u : (u | 0x80000000u);
}

// ===== K0: h = x . W (Eigen NEON gemv arithmetic), one thread per row =====
__global__ __launch_bounds__(256)
void k0_linear(const float* __restrict__ x, const float* __restrict__ Wp,
               long long Nrows)
{
    __shared__ float wsh[CC];
    if (threadIdx.x < CC) wsh[threadIdx.x] = Wp[threadIdx.x];
    __syncthreads();
    long long row = (long long)blockIdx.x * 256 + threadIdx.x;
    if (row >= Nrows) return;
    const float4* w4 = (const float4*)wsh;
    const float4* xr = (const float4*)(x + row * CC);
    float a0 = 0.f, a1 = 0.f, a2 = 0.f, a3 = 0.f;
    #pragma unroll 4
    for (int i = 0; i < 64; i++) {
        float4 v = xr[i];
        float4 w = w4[i];
        a0 = fmaf(v.x, w.x, a0);
        a1 = fmaf(v.y, w.y, a1);
        a2 = fmaf(v.z, w.z, a2);
        a3 = fmaf(v.w, w.w, a3);
    }
    g_h[row] = __fadd_rn(__fadd_rn(a0, a2), __fadd_rn(a1, a3));
}

// ===== K1a: edge pack + stable counting sort by dst (no h needed) =====
__global__ __launch_bounds__(NT1, 3)
void k1a_sort(const void* __restrict__ edge_index, long long E, int epg)
{
    extern __shared__ char smem[];
    int* indeg_s = (int*)smem;                           // RRP
    int* start_s = indeg_s + RRP;                        // RRP
    int* flag_s  = start_s + RRP;                        // 8
    unsigned short* hist = (unsigned short*)(flag_s + 8);      // NW1*HB
    unsigned int* ed = (unsigned int*)(((size_t)(hist + NW1 * HB) + 7) & ~(size_t)7);
    unsigned short* ssrc = (unsigned short*)(ed + epg);

    const int tid  = threadIdx.x;
    const int lane = tid & 31;
    const int warp = tid >> 5;
    const int g    = blockIdx.x;
    const long long gbase = (long long)g * RR;
    const long long ebase = (long long)g * epg;

    for (int i = tid; i < NW1 * HB; i += NT1) hist[i] = 0;
    if (tid == 0) {
        const int* p32 = (const int*)edge_index;
        int all_zero = 1;
        #pragma unroll
        for (int i = 1; i < 32; i += 2)
            if (p32[i] != 0) { all_zero = 0; break; }
        *flag_s = all_zero;
    }
    __syncthreads();
    const int is64 = *flag_s;

    if (is64) {
        const long long* p = (const long long*)edge_index;
        for (int e = tid; e < epg; e += NT1) {
            int ls = (int)(p[ebase + e] - gbase);
            int ld = (int)(p[ebase + E + e] - gbase);
            unsigned pk = ((unsigned)ls << 16) | (unsigned)ld;
            ed[e] = pk;
            g_packed[ebase + e] = pk;
        }
    } else {
        const int* p = (const int*)edge_index;
        for (int e = tid; e < epg; e += NT1) {
            int ls = (int)(p[ebase + e] - gbase);
            int ld = (int)(p[ebase + E + e] - gbase);
            unsigned pk = ((unsigned)ls << 16) | (unsigned)ld;
            ed[e] = pk;
            g_packed[ebase + e] = pk;
        }
    }
    __syncthreads();

    const int per = (((epg + NW1 - 1) / NW1) + 31) & ~31;
    const int cbeg = warp * per;
    const int cend = min(epg, cbeg + per);

    // pass 1: per-warp-chunk histograms (deterministic)
    for (int base = cbeg; base < cend; base += 32) {
        int e = base + lane;
        bool act = e < cend;
        unsigned v = act ? ed[e] : 0u;
        int dst = act ? (int)(v & 0xFFFFu) : (512 + lane);
        unsigned m = __match_any_sync(FULLM, dst);
        int leader = __ffs(m) - 1;
        if (act && lane == leader)
            hist[warp * HB + dst] = (unsigned short)(hist[warp * HB + dst] + __popc(m));
        __syncwarp();
    }
    __syncthreads();

    for (int v = tid; v < RR; v += NT1) {
        int s = 0;
        #pragma unroll
        for (int w2 = 0; w2 < NW1; w2++) s += hist[w2 * HB + v];
        indeg_s[v] = s;
    }
    __syncthreads();

    if (warp == 0) {
        int lo = lane * 9;
        int acc = 0;
        #pragma unroll
        for (int i = 0; i < 9; i++) { int v = lo + i; if (v < RR) acc += indeg_s[v]; }
        int ex = acc;
        #pragma unroll
        for (int o = 1; o < 32; o <<= 1) {
            int t = __shfl_up_sync(FULLM, ex, o);
            if (lane >= o) ex += t;
        }
        ex -= acc;
        int run = ex;
        #pragma unroll
        for (int i = 0; i < 9; i++) {
            int v = lo + i;
            if (v < RR) { start_s[v] = run; run += indeg_s[v]; }
        }
    }
    __syncthreads();

    for (int v = tid; v < RR; v += NT1) {
        int s = start_s[v];
        #pragma unroll
        for (int w2 = 0; w2 < NW1; w2++) {
            int t = hist[w2 * HB + v];
            hist[w2 * HB + v] = (unsigned short)s;
            s += t;
        }
    }
    __syncthreads();

    // pass 2: stable placement
    for (int base = cbeg; base < cend; base += 32) {
        int e = base + lane;
        bool act = e < cend;
        unsigned v = act ? ed[e] : 0u;
        int dst = act ? (int)(v & 0xFFFFu) : (512 + lane);
        unsigned m = __match_any_sync(FULLM, dst);
        int rank = __popc(m & ((1u << lane) - 1u));
        int pos = 0;
        if (act) pos = (int)hist[warp * HB + dst] + rank;
        __syncwarp();
        if (act) ssrc[pos] = (unsigned short)(v >> 16);
        int leader = __ffs(m) - 1;
        if (act && lane == leader)
            hist[warp * HB + dst] = (unsigned short)(hist[warp * HB + dst] + __popc(m));
        __syncwarp();
    }
    __syncthreads();

    // export sorted lists + per-node offsets (coalesced u32 stores)
    {
        unsigned int* dst32 = (unsigned int*)&g_ssrc[ebase];
        const unsigned int* src32 = (const unsigned int*)ssrc;
        for (int i = tid; i < (epg >> 1); i += NT1) dst32[i] = src32[i];
    }
    for (int v = tid; v < RR; v += NT1) {
        g_indeg[g * RRP + v] = (unsigned short)indeg_s[v];
        g_start[g * RRP + v] = (unsigned short)start_s[v];
    }
}

// ===== K1b: score (bit-exact reference order) + rank-based top-K =====
__global__ __launch_bounds__(NT1)
void k1b_score(const float* __restrict__ bp, float* __restrict__ out,
               int epg, size_t off_score)
{
    extern __shared__ char smem[];
    unsigned short* ssrc_s = (unsigned short*)smem;        // epg u16
    float* h_s   = (float*)(ssrc_s + epg);                 // RRP
    float* dis_s = h_s + RRP;                              // RRP
    float* sc_s  = dis_s + RRP;                            // RRP
    int* start_sh = (int*)(sc_s + RRP);                    // RRP
    int* indeg_sh = start_sh + RRP;                        // RRP
    unsigned long long* keys =
        (unsigned long long*)(((size_t)(indeg_sh + RRP) + 7) & ~(size_t)7); // RRP

    const int tid = threadIdx.x;
    const int g = blockIdx.x;
    const long long gbase = (long long)g * RR;
    const long long ebase = (long long)g * epg;

    // stage sorted src lists (coalesced u32 loads)
    {
        const unsigned int* src32 = (const unsigned int*)&g_ssrc[ebase];
        unsigned int* dst32 = (unsigned int*)ssrc_s;
        for (int i = tid; i < (epg >> 1); i += NT1) dst32[i] = src32[i];
    }
    for (int v = tid; v < RR; v += NT1) {
        h_s[v] = g_h[gbase + v];
        int n = g_indeg[g * RRP + v];
        indeg_sh[v] = n;
        start_sh[v] = g_start[g * RRP + v];
        dis_s[v] = __fdiv_rn(1.0f, __fsqrt_rn((float)(n + 1)));
    }
    __syncthreads();

    const float bval = bp[0];
    for (int v = tid; v < RR; v += NT1) {
        float dv = dis_s[v];
        float acc = 0.f;
        int st = start_sh[v], n = indeg_sh[v];
        for (int i = 0; i < n; i++) {
            int src = ssrc_s[st + i];
            float c = __fmul_rn(__fmul_rn(dis_s[src], dv), h_s[src]);
            acc = __fadd_rn(acc, c);
        }
        float selfc = __fmul_rn(__fmul_rn(dv, dv), h_s[v]);
        acc = __fadd_rn(acc, selfc);
        float sc = __fadd_rn(acc, bval);
        sc_s[v] = sc;
        out[off_score + (size_t)gbase + v] = sc;
        keys[v] = ((unsigned long long)ord_f32(sc) << 32)
                  | (unsigned long long)(0x1FFu - (unsigned)v);
    }
    __syncthreads();

    for (int v = tid; v < RR; v += NT1) {
        unsigned long long mk = keys[v];
        int rank = 0;
        #pragma unroll 3
        for (int u = 0; u < RR; u++)
            rank += (keys[u] > mk) ? 1 : 0;
        short nid = (rank < KK) ? (short)rank : (short)-1;
        g_newid[g * RRP + v] = nid;
        if (rank < KK) g_sel[g * KKP + rank] = (unsigned short)v;
    }
}

// ===== K2: gather x_new / perm / batch (one warp per output row) =====
__global__ __launch_bounds__(256)
void k2_gather(const float* __restrict__ x, float* __restrict__ out,
               size_t off_batch, size_t off_perm, size_t off_score,
               int total_rows)
{
    const int lane = threadIdx.x & 31;
    const int wid  = blockIdx.x * 8 + (threadIdx.x >> 5);
    if (wid >= total_rows) return;
    const int g = wid / KK;
    const int k = wid - g * KK;
    const int v = g_sel[g * KKP + k];
    const long long gbase = (long long)g * RR;
    float sc = out[off_score + (size_t)gbase + v];
    float t = tanhf(sc);
    const float4* srcp = (const float4*)(x + ((size_t)(gbase + v)) * CC);
    float4* dstp = (float4*)(out + (size_t)wid * CC);
    float4 a0 = srcp[lane];
    float4 a1 = srcp[lane + 32];
    a0.x *= t; a0.y *= t; a0.z *= t; a0.w *= t;
    a1.x *= t; a1.y *= t; a1.z *= t; a1.w *= t;
    dstp[lane] = a0;
    dstp[lane + 32] = a1;
    if (lane == 0) {
        out[off_perm  + wid] = (float)(gbase + v);
        out[off_batch + wid] = (float)g;
    }
}

// ===== K3: edge remap + keep (one block per graph) =====
__global__ __launch_bounds__(256)
void k3_remap(float* __restrict__ out,
              long long E, int epg, size_t off_ei, size_t off_keep)
{
    __shared__ short nid[RRP];
    const int tid = threadIdx.x;
    const int g = blockIdx.x;
    for (int v = tid; v < RR; v += 256) nid[v] = g_newid[g * RRP + v];
    __syncthreads();
    const size_t ebase = (size_t)g * epg;
    const int gk = g * KK;
    for (int e = tid; e < epg; e += 256) {
        unsigned v = g_packed[ebase + e];
        int ns = nid[v >> 16];
        int nd = nid[v & 0xFFFFu];
        size_t ge = ebase + e;
        bool kp = (ns >= 0) & (nd >= 0);
        out[off_ei + ge]             = kp ? (float)(gk + ns) : -1.0f;
        out[off_ei + (size_t)E + ge] = kp ? (float)(gk + nd) : -1.0f;
        out[off_keep + ge]           = kp ? 1.0f : 0.0f;
    }
}

extern "C" void kernel_launch(void* const* d_in, const int* in_sizes, int n_in,
                              void* d_out, int out_size)
{
    const float* x  = (const float*)d_in[0];
    const void*  ei = d_in[1];
    const float* W  = (const float*)d_in[3];
    const float* b  = (const float*)d_in[4];

    long long N = (long long)in_sizes[0] / CC;
    long long E = (long long)in_sizes[1] / 2;
    int G   = (int)(N / RR);
    int epg = (int)(E / G);

    float* out = (float*)d_out;
    size_t GK        = (size_t)G * KK;
    size_t off_ei    = GK * CC;
    size_t off_keep  = off_ei + 2 * (size_t)E;
    size_t off_batch = off_keep + (size_t)E;
    size_t off_perm  = off_batch + GK;
    size_t off_score = off_perm + GK;

    // K1a dynamic smem
    size_t fixed = 2 * RRP * 4 + 8 * 4 + (size_t)NW1 * HB * 2 + 8;
    size_t smem1a = fixed + (size_t)epg * 4 + (size_t)epg * 2 + 64;
    // K1b dynamic smem
    size_t smem1b = (size_t)epg * 2 + 5 * RRP * 4 + RRP * 8 + 64;

    static cudaStream_t s2 = 0;
    static cudaEvent_t evF1 = 0, evJ1 = 0, evF2 = 0, evJ2 = 0;
    static int init_done = 0;
    if (!init_done) {
        cudaFuncSetAttribute(k1a_sort,
                             cudaFuncAttributeMaxDynamicSharedMemorySize,
                             (int)smem1a);
        cudaFuncSetAttribute(k1b_score,
                             cudaFuncAttributeMaxDynamicSharedMemorySize,
                             (int)smem1b);
        cudaStreamCreateWithFlags(&s2, cudaStreamNonBlocking);
        cudaEventCreateWithFlags(&evF1, cudaEventDisableTiming);
        cudaEventCreateWithFlags(&evJ1, cudaEventDisableTiming);
        cudaEventCreateWithFlags(&evF2, cudaEventDisableTiming);
        cudaEventCreateWithFlags(&evJ2, cudaEventDisableTiming);
        init_done = 1;
    }

    int gridK0 = (int)((N + 255) / 256);
    int totalRows = (int)GK;
    int gridK2 = (totalRows + 7) / 8;

    // fork 1: K0 (stream 0) || K1a (s2)
    cudaEventRecord(evF1, 0);
    cudaStreamWaitEvent(s2, evF1, 0);
    k0_linear<<<gridK0, 256, 0, 0>>>(x, W, N);
    k1a_sort<<<G, NT1, smem1a, s2>>>(ei, E, epg);
    cudaEventRecord(evJ1, s2);
    cudaStreamWaitEvent(0, evJ1, 0);

    // K1b (stream 0, needs h + sorted lists)
    k1b_score<<<G, NT1, smem1b, 0>>>(b, out, epg, off_score);

    // fork 2: K2 (stream 0) || K3 (s2)
    cudaEventRecord(evF2, 0);
    cudaStreamWaitEvent(s2, evF2, 0);
    k2_gather<<<gridK2, 256, 0, 0>>>(x, out, off_batch, off_perm, off_score, totalRows);
    k3_remap<<<G, 256, 0, s2>>>(out, E, epg, off_ei, off_keep);
    cudaEventRecord(evJ2, s2);
    cudaStreamWaitEvent(0, evJ2, 0);
}

// round 17
// speedup vs baseline: 1.1828x; 1.1331x over previous
#include <cuda_runtime.h>
#include <math.h>

#define RR 273
#define CC 256
#define KK 219
#define KKP 224
#define RRP 288
#define NTHREADS 384
#define NWARPS 12
#define HB 280
#define FULLM 0xFFFFFFFFu
#define GMAX 1024
#define EMAX (GMAX * 273 * 32)

__device__ unsigned int   g_packed[EMAX];       // packed local ids (src<<16|dst)
__device__ unsigned short g_sel[GMAX * KKP];    // rank -> node id
__device__ short          g_newid[GMAX * RRP];  // node -> new id (-1 dropped)

__device__ __forceinline__ unsigned int ord_f32(float f) {
    unsigned int u = __float_as_uint(f);
    return (u & 0x80000000u) ? ~u : (u | 0x80000000u);
}

// ===== front: h (Eigen-exact gemv) + edge pack + counting sort + score + rank =====
__global__ __launch_bounds__(NTHREADS, 3)
void k_front(const float* __restrict__ x,
             const void*  __restrict__ edge_index,
             const float* __restrict__ Wp,
             const float* __restrict__ bp,
             float* __restrict__ out,
             long long E, int epg, size_t off_score)
{
    extern __shared__ char smem[];
    float* wsh   = (float*)smem;                        // 256 floats
    float* h_s   = wsh + CC;                            // 288
    float* dis_s = h_s + 288;                           // 288
    float* sc_s  = dis_s + 288;                         // 288
    int* indeg_s = (int*)(sc_s + 288);                  // 288
    int* start_s = indeg_s + 288;                       // 288
    int* newid_s = start_s + 288;                       // 288
    int* flag_s  = newid_s + 288;                       // 8
    unsigned short* hist = (unsigned short*)(flag_s + 8);      // NWARPS*HB u16
    unsigned int* ed = (unsigned int*)(((size_t)(hist + NWARPS * HB) + 7) & ~(size_t)7); // epg
    char* ub = (char*)(ed + epg);
    unsigned short* ssrc = (unsigned short*)ub;                 // epg u16 (thru score)
    unsigned long long* keys = (unsigned long long*)ub;         // 288 u64 (after)
    unsigned short* sel = (unsigned short*)(keys + 288);        // KKP u16

    const int tid  = threadIdx.x;
    const int lane = tid & 31;
    const int warp = tid >> 5;
    const int g    = blockIdx.x;
    const long long gbase = (long long)g * RR;

    // stage W, init, self-probe dtype
    if (tid < CC) wsh[tid] = Wp[tid];
    for (int i = tid; i < NWARPS * HB; i += NTHREADS) hist[i] = 0;
    if (tid == 0) {
        const int* p32 = (const int*)edge_index;
        int all_zero = 1;
        #pragma unroll
        for (int i = 1; i < 32; i += 2)
            if (p32[i] != 0) { all_zero = 0; break; }
        *flag_s = all_zero;
    }
    __syncthreads();
    const int is64 = *flag_s;

    // phase A: h[v] as Eigen NEON row-major gemv (evalGemv):
    // 4-lane packet acc, vfmaq (fused), predux (a0+a2)+(a1+a3); one row/thread
    if (tid < RR) {
        const float4* w4 = (const float4*)wsh;
        const float4* xr = (const float4*)(x + ((size_t)(gbase + tid)) * CC);
        float a0 = 0.f, a1 = 0.f, a2 = 0.f, a3 = 0.f;
        #pragma unroll 4
        for (int i = 0; i < 64; i++) {
            float4 v = xr[i];
            float4 w = w4[i];
            a0 = fmaf(v.x, w.x, a0);
            a1 = fmaf(v.y, w.y, a1);
            a2 = fmaf(v.z, w.z, a2);
            a3 = fmaf(v.w, w.w, a3);
        }
        h_s[tid] = __fadd_rn(__fadd_rn(a0, a2), __fadd_rn(a1, a3));
    }

    // edge load -> packed local ids (smem + gmem scratch for K3)
    {
        const long long ebase = (long long)g * epg;
        if (is64) {
            const long long* p = (const long long*)edge_index;
            for (int e = tid; e < epg; e += NTHREADS) {
                int ls = (int)(p[ebase + e] - gbase);
                int ld = (int)(p[ebase + E + e] - gbase);
                unsigned pk = ((unsigned)ls << 16) | (unsigned)ld;
                ed[e] = pk;
                g_packed[ebase + e] = pk;
            }
        } else {
            const int* p = (const int*)edge_index;
            for (int e = tid; e < epg; e += NTHREADS) {
                int ls = (int)(p[ebase + e] - gbase);
                int ld = (int)(p[ebase + E + e] - gbase);
                unsigned pk = ((unsigned)ls << 16) | (unsigned)ld;
                ed[e] = pk;
                g_packed[ebase + e] = pk;
            }
        }
    }
    __syncthreads();   // h_s, ed ready

    // stable counting sort by dst
    const int per = (((epg + NWARPS - 1) / NWARPS) + 31) & ~31;
    const int cbeg = warp * per;
    const int cend = min(epg, cbeg + per);

    for (int base = cbeg; base < cend; base += 32) {
        int e = base + lane;
        bool act = e < cend;
        unsigned v = act ? ed[e] : 0u;
        int dst = act ? (int)(v & 0xFFFFu) : (512 + lane);
        unsigned m = __match_any_sync(FULLM, dst);
        int leader = __ffs(m) - 1;
        if (act && lane == leader)
            hist[warp * HB + dst] = (unsigned short)(hist[warp * HB + dst] + __popc(m));
        __syncwarp();
    }
    __syncthreads();

    for (int v = tid; v < RR; v += NTHREADS) {
        int s = 0;
        #pragma unroll
        for (int w2 = 0; w2 < NWARPS; w2++) s += hist[w2 * HB + v];
        indeg_s[v] = s;
        dis_s[v] = __fdiv_rn(1.0f, __fsqrt_rn((float)(s + 1)));
    }
    __syncthreads();

    if (warp == 0) {
        int lo = lane * 9;
        int acc = 0;
        #pragma unroll
        for (int i = 0; i < 9; i++) { int v = lo + i; if (v < RR) acc += indeg_s[v]; }
        int ex = acc;
        #pragma unroll
        for (int o = 1; o < 32; o <<= 1) {
            int t = __shfl_up_sync(FULLM, ex, o);
            if (lane >= o) ex += t;
        }
        ex -= acc;
        int run = ex;
        #pragma unroll
        for (int i = 0; i < 9; i++) {
            int v = lo + i;
            if (v < RR) { start_s[v] = run; run += indeg_s[v]; }
        }
    }
    __syncthreads();

    for (int v = tid; v < RR; v += NTHREADS) {
        int s = start_s[v];
        #pragma unroll
        for (int w2 = 0; w2 < NWARPS; w2++) {
            int t = hist[w2 * HB + v];
            hist[w2 * HB + v] = (unsigned short)s;
            s += t;
        }
    }
    __syncthreads();

    for (int base = cbeg; base < cend; base += 32) {
        int e = base + lane;
        bool act = e < cend;
        unsigned v = act ? ed[e] : 0u;
        int dst = act ? (int)(v & 0xFFFFu) : (512 + lane);
        unsigned m = __match_any_sync(FULLM, dst);
        int rank = __popc(m & ((1u << lane) - 1u));
        int pos = 0;
        if (act) pos = (int)hist[warp * HB + dst] + rank;
        __syncwarp();
        if (act) ssrc[pos] = (unsigned short)(v >> 16);
        int leader = __ffs(m) - 1;
        if (act && lane == leader)
            hist[warp * HB + dst] = (unsigned short)(hist[warp * HB + dst] + __popc(m));
        __syncwarp();
    }
    __syncthreads();

    // score: strictly sequential in reference scatter order
    const float bval = bp[0];
    if (tid < RR) {
        int v = tid;
        float dv = dis_s[v];
        float acc = 0.f;
        int st = start_s[v], n = indeg_s[v];
        for (int i = 0; i < n; i++) {
            int src = ssrc[st + i];
            float c = __fmul_rn(__fmul_rn(dis_s[src], dv), h_s[src]);
            acc = __fadd_rn(acc, c);
        }
        float selfc = __fmul_rn(__fmul_rn(dv, dv), h_s[v]);
        acc = __fadd_rn(acc, selfc);
        float sc = __fadd_rn(acc, bval);
        sc_s[v] = sc;
        out[off_score + (size_t)gbase + v] = sc;
    }
    __syncthreads();   // ssrc dead

    // rank keys (unique via index tie-break)
    if (tid < RR) {
        keys[tid] = ((unsigned long long)ord_f32(sc_s[tid]) << 32)
                    | (unsigned long long)(0x1FFu - (unsigned)tid);
        newid_s[tid] = -1;
    }
    __syncthreads();

    // rank-based top-K selection
    if (tid < RR) {
        unsigned long long mk = keys[tid];
        int rank = 0;
        #pragma unroll 3
        for (int u = 0; u < RR; u++)
            rank += (keys[u] > mk) ? 1 : 0;
        if (rank < KK) {
            newid_s[tid] = rank;
            sel[rank] = (unsigned short)tid;
        }
    }
    __syncthreads();

    // export sel + newid for K2/K3
    if (tid < RR) g_newid[g * RRP + tid] = (short)newid_s[tid];
    if (tid < KK) g_sel[g * KKP + tid] = sel[tid];
}

// ===== K2: gather x_new / perm / batch (one warp per output row) =====
__global__ __launch_bounds__(256)
void k2_gather(const float* __restrict__ x, float* __restrict__ out,
               size_t off_batch, size_t off_perm, size_t off_score,
               int total_rows)
{
    const int lane = threadIdx.x & 31;
    const int wid  = blockIdx.x * 8 + (threadIdx.x >> 5);
    if (wid >= total_rows) return;
    const int g = wid / KK;
    const int k = wid - g * KK;
    const int v = g_sel[g * KKP + k];
    const long long gbase = (long long)g * RR;
    float sc = out[off_score + (size_t)gbase + v];
    float t = tanhf(sc);
    const float4* srcp = (const float4*)(x + ((size_t)(gbase + v)) * CC);
    float4* dstp = (float4*)(out + (size_t)wid * CC);
    float4 a0 = srcp[lane];
    float4 a1 = srcp[lane + 32];
    a0.x *= t; a0.y *= t; a0.z *= t; a0.w *= t;
    a1.x *= t; a1.y *= t; a1.z *= t; a1.w *= t;
    dstp[lane] = a0;
    dstp[lane + 32] = a1;
    if (lane == 0) {
        out[off_perm  + wid] = (float)(gbase + v);
        out[off_batch + wid] = (float)g;
    }
}

// ===== K3: edge remap + keep (one block per graph) =====
__global__ __launch_bounds__(256)
void k3_remap(float* __restrict__ out,
              long long E, int epg, size_t off_ei, size_t off_keep)
{
    __shared__ short nid[RRP];
    const int tid = threadIdx.x;
    const int g = blockIdx.x;
    for (int v = tid; v < RR; v += 256) nid[v] = g_newid[g * RRP + v];
    __syncthreads();
    const size_t ebase = (size_t)g * epg;
    const int gk = g * KK;
    for (int e = tid; e < epg; e += 256) {
        unsigned v = g_packed[ebase + e];
        int ns = nid[v >> 16];
        int nd = nid[v & 0xFFFFu];
        size_t ge = ebase + e;
        bool kp = (ns >= 0) & (nd >= 0);
        out[off_ei + ge]             = kp ? (float)(gk + ns) : -1.0f;
        out[off_ei + (size_t)E + ge] = kp ? (float)(gk + nd) : -1.0f;
        out[off_keep + ge]           = kp ? 1.0f : 0.0f;
    }
}

extern "C" void kernel_launch(void* const* d_in, const int* in_sizes, int n_in,
                              void* d_out, int out_size)
{
    const float* x  = (const float*)d_in[0];
    const void*  ei = d_in[1];
    const float* W  = (const float*)d_in[3];
    const float* b  = (const float*)d_in[4];

    long long N = (long long)in_sizes[0] / CC;
    long long E = (long long)in_sizes[1] / 2;
    int G   = (int)(N / RR);
    int epg = (int)(E / G);

    float* out = (float*)d_out;
    size_t GK        = (size_t)G * KK;
    size_t off_ei    = GK * CC;
    size_t off_keep  = off_ei + 2 * (size_t)E;
    size_t off_batch = off_keep + (size_t)E;
    size_t off_perm  = off_batch + GK;
    size_t off_score = off_perm + GK;

    // front kernel dynamic smem (must match kernel layout)
    size_t fixed = (size_t)CC * 4 + 6 * 288 * 4 + 8 * 4 + (size_t)NWARPS * HB * 2 + 8;
    size_t edB   = (size_t)epg * 4;
    size_t keysB = 288 * 8 + (size_t)KKP * 2;
    size_t uB    = ((size_t)epg * 2 > keysB) ? (size_t)epg * 2 : keysB;
    size_t smemF = fixed + edB + uB + 64;

    static int attr_set = 0;
    if (!attr_set) {
        cudaFuncSetAttribute(k_front,
                             cudaFuncAttributeMaxDynamicSharedMemorySize,
                             (int)smemF);
        attr_set = 1;
    }

    int totalRows = (int)GK;
    int gridK2 = (totalRows + 7) / 8;

    k_front<<<G, NTHREADS, smemF>>>(x, ei, W, b, out, E, epg, off_score);
    k2_gather<<<gridK2, 256>>>(x, out, off_batch, off_perm, off_score, totalRows);
    k3_remap<<<G, 256>>>(out, E, epg, off_ei, off_keep);
}